// round 11
// baseline (speedup 1.0000x reference)
#include <cuda_runtime.h>
#include <stdint.h>

#define NUM_BINS   256
#define GRID       152                 // GB300: 152 SMs, 1 resident block each
#define NC_WARPS   4                   // consumer warps (own histograms)
#define NWARPS_TOT 5                   // + 1 producer warp
#define CTHREADS   (NC_WARPS * 32)     // 128
#define NTHREADS   (NWARPS_TOT * 32)   // 160

#define HIST_F32_PER_WARP (NUM_BINS * 32)            // 8192 floats = 32 KB
#define HIST_FLOATS (NC_WARPS * HIST_F32_PER_WARP)   // 32768
#define HIST_BYTES  (HIST_FLOATS * 4)                // 131072

#define GPT         6                  // float4-groups per consumer thread per slot
#define SLOT_G      (CTHREADS * GPT)   // 768 groups = 3072 elements
#define SLOT_HALF   (SLOT_G * 16)      // 12288 B (x half; idx half same)
#define SLOT_BYTES  (SLOT_G * 32)      // 24576 B
#define NSLOTS      4
#define RING_BYTES  (NSLOTS * SLOT_BYTES)            // 98304
#define MBAR_BYTES  128
#define SMEM_BYTES  (HIST_BYTES + RING_BYTES + MBAR_BYTES)  // 229504 <= 232448

#define BIAS 1024.0f
#define INV_BIAS (1.0f / 1024.0f)

// per-block partial results + completion ticket (no cudaMalloc allowed)
__device__ float g_psum[GRID * NUM_BINS];
__device__ float g_pcnt[GRID * NUM_BINS];
__device__ int   g_ticket = 0;

__device__ __forceinline__ uint32_t smem_u32(const void* p) {
    return (uint32_t)__cvta_generic_to_shared(p);
}
__device__ __forceinline__ void mbar_init(uint32_t mbar, uint32_t cnt) {
    asm volatile("mbarrier.init.shared.b64 [%0], %1;" :: "r"(mbar), "r"(cnt) : "memory");
}
__device__ __forceinline__ void mbar_arrive(uint32_t mbar) {
    asm volatile("mbarrier.arrive.shared.b64 _, [%0];" :: "r"(mbar) : "memory");
}
__device__ __forceinline__ void mbar_expect_tx(uint32_t mbar, uint32_t bytes) {
    asm volatile("mbarrier.arrive.expect_tx.shared.b64 _, [%0], %1;"
                 :: "r"(mbar), "r"(bytes) : "memory");
}
__device__ __forceinline__ void mbar_wait(uint32_t mbar, uint32_t phase) {
    asm volatile(
        "{\n\t"
        ".reg .pred P1;\n\t"
        "WAIT_LOOP_%=:\n\t"
        "mbarrier.try_wait.parity.acquire.cta.shared::cta.b64 P1, [%0], %1, 0x989680;\n\t"
        "@P1 bra.uni WAIT_DONE_%=;\n\t"
        "bra.uni WAIT_LOOP_%=;\n\t"
        "WAIT_DONE_%=:\n\t"
        "}"
        :: "r"(mbar), "r"(phase) : "memory");
}
__device__ __forceinline__ void bulk_g2s(uint32_t sdst, const void* gsrc,
                                         uint32_t bytes, uint32_t mbar) {
    asm volatile(
        "cp.async.bulk.shared::cta.global.mbarrier::complete_tx::bytes "
        "[%0], [%1], %2, [%3];"
        :: "r"(sdst), "l"(gsrc), "r"(bytes), "r"(mbar) : "memory");
}

// 4-way wave: exact dedup in registers, then 4 batched LDS + <=4 predicated STS.
__device__ __forceinline__ void rmw4d(float* hb, float4 xv, int4 iv) {
    int b0 = iv.x & 255, b1 = iv.y & 255, b2 = iv.z & 255, b3 = iv.w & 255;
    float v0 = xv.x + BIAS, v1 = xv.y + BIAS, v2 = xv.z + BIAS, v3 = xv.w + BIAS;

    bool l1 = (b1 != b0);
    if (!l1) v0 += v1;

    bool e20 = (b2 == b0);
    bool e21 = (b2 == b1) && l1;
    bool l2  = !(e20 || e21);
    if (e20) v0 += v2;
    if (e21) v1 += v2;

    bool e30 = (b3 == b0);
    bool e31 = (b3 == b1) && l1;
    bool e32 = (b3 == b2) && l2;
    bool l3  = !(e30 || e31 || e32);
    if (e30) v0 += v3;
    if (e31) v1 += v3;
    if (e32) v2 += v3;

    float* p0 = hb + (b0 << 5);
    float* p1 = hb + (b1 << 5);
    float* p2 = hb + (b2 << 5);
    float* p3 = hb + (b3 << 5);
    float e0 = *p0;
    float f1 = *p1;
    float f2 = *p2;
    float f3 = *p3;
    *p0 = e0 + v0;
    if (l1) *p1 = f1 + v1;
    if (l2) *p2 = f2 + v2;
    if (l3) *p3 = f3 + v3;
}

__global__ __launch_bounds__(NTHREADS, 1)
void seg_hist_kernel(const float* __restrict__ x,
                     const int*   __restrict__ idx,
                     const float* __restrict__ target_mean,
                     float* __restrict__ out,
                     int E)
{
    extern __shared__ float smem[];
    const int tid  = threadIdx.x;
    const int lane = tid & 31;
    const int warp = tid >> 5;
    const int bid  = blockIdx.x;

    char*    ring = (char*)smem + HIST_BYTES;
    uint32_t mb   = smem_u32((char*)smem + HIST_BYTES + RING_BYTES);
    // full[s] = mb + s*16 ; empty[s] = mb + s*16 + 8

    // zero the private histograms (vectorized)
    float4* sz = (float4*)smem;
    #pragma unroll 4
    for (int i = tid; i < HIST_FLOATS / 4; i += NTHREADS)
        sz[i] = make_float4(0.f, 0.f, 0.f, 0.f);

    if (tid == 0) {
        #pragma unroll
        for (int s = 0; s < NSLOTS; s++) {
            mbar_init(mb + s * 16,     1);         // full: producer expect_tx
            mbar_init(mb + s * 16 + 8, NC_WARPS);  // empty: 1 arrive per consumer warp
        }
    }
    __syncthreads();

    const float4* __restrict__ x4 = (const float4*)x;
    const int4*   __restrict__ i4 = (const int4*)idx;
    const int G = E >> 2;                        // float4 groups (2^23)
    const int total_slots = G / SLOT_G;          // 10922
    const int tail_start  = total_slots * SLOT_G;
    const int nslots = total_slots / GRID + (bid < (total_slots % GRID) ? 1 : 0);

    if (warp < NC_WARPS) {
        // ── consumer: wait full, drain contiguous slot, 1 elected empty-arrive
        float* hb = smem + warp * HIST_F32_PER_WARP + lane;
        int s = 0, ph = 0;
        for (int i = 0; i < nslots; ++i) {
            mbar_wait(mb + s * 16, ph);
            const char* sl = ring + s * SLOT_BYTES;
            // software-pipelined staged loads: load wave k+1 before rmw of wave k
            float4 a = *(const float4*)(sl + tid * 16);
            int4   b = *(const int4*)(sl + SLOT_HALF + tid * 16);
            #pragma unroll
            for (int k = 0; k < GPT - 1; k++) {
                float4 an = *(const float4*)(sl + ((k + 1) * CTHREADS + tid) * 16);
                int4   bn = *(const int4*)(sl + SLOT_HALF + ((k + 1) * CTHREADS + tid) * 16);
                rmw4d(hb, a, b);
                a = an; b = bn;
            }
            rmw4d(hb, a, b);
            __syncwarp();
            if (lane == 0) mbar_arrive(mb + s * 16 + 8);
            if (++s == NSLOTS) { s = 0; ph ^= 1; }
        }
        // tail groups beyond full slots (direct bounds-checked loads)
        for (int g = tail_start + bid * CTHREADS + tid; g < G; g += GRID * CTHREADS)
            rmw4d(hb, __ldcs(&x4[g]), __ldcs(&i4[g]));

        // sub-float4 remainder: block 0, consumer warp 0
        int rem = E & 3;
        if (rem && bid == 0 && warp == 0 && lane < rem) {
            int e = (E & ~3) + lane;
            float v = x[e] + BIAS;
            float* p = hb + ((idx[e] & 255) << 5);
            *p = *p + v;
        }
    } else if (lane == 0) {
        // ── producer: single thread; bulk-copy contiguous slots, expect_tx.
        // Up to NSLOTS-1 fills in flight -> completion latency hidden.
        int s = 0, ph = 1;                 // phase 1: first empty-wait passes
        for (int i = 0; i < nslots; ++i) {
            mbar_wait(mb + s * 16 + 8, ph);
            int sid = bid + i * GRID;
            uint32_t sdst = smem_u32(ring + s * SLOT_BYTES);
            mbar_expect_tx(mb + s * 16, SLOT_BYTES);
            bulk_g2s(sdst,             &x4[(size_t)sid * SLOT_G], SLOT_HALF, mb + s * 16);
            bulk_g2s(sdst + SLOT_HALF, &i4[(size_t)sid * SLOT_G], SLOT_HALF, mb + s * 16);
            if (++s == NSLOTS) { s = 0; ph ^= 1; }
        }
    }
    __syncthreads();

    // block reduction: NC_WARPS*32 lane-columns -> 1 (sum, count) per bin
    for (int bin = tid; bin < NUM_BINS; bin += NTHREADS) {
        float s = 0.0f, c = 0.0f;
        #pragma unroll
        for (int w = 0; w < NC_WARPS; w++) {
            const float* bptr = smem + w * HIST_F32_PER_WARP + (bin << 5);
            #pragma unroll
            for (int k = 0; k < 32; k++) {
                int l = (bin + k) & 31;          // rotated, conflict-free
                float e = bptr[l];
                float cc = rintf(e * INV_BIAS);  // recover count
                s += e - cc * BIAS;              // recover sum(x)
                c += cc;
            }
        }
        g_psum[bid * NUM_BINS + bin] = s;
        g_pcnt[bid * NUM_BINS + bin] = c;
    }
    __syncthreads();
    __threadfence();

    // last block finishes the reduction
    __shared__ int s_last;
    if (tid == 0)
        s_last = (atomicAdd(&g_ticket, 1) == GRID - 1) ? 1 : 0;
    __syncthreads();
    if (!s_last) return;

    // warp w sums blocks {w, w+5, ...} for all 256 bins (coalesced, L2-hot)
    float accS[8], accC[8];
    #pragma unroll
    for (int j = 0; j < 8; j++) { accS[j] = 0.f; accC[j] = 0.f; }
    for (int blk = warp; blk < GRID; blk += NWARPS_TOT) {
        #pragma unroll
        for (int j = 0; j < 8; j++) {
            int bin = lane + j * 32;
            accS[j] += g_psum[blk * NUM_BINS + bin];
            accC[j] += g_pcnt[blk * NUM_BINS + bin];
        }
    }
    float* sS  = smem;                          // [5][256]
    float* sC  = smem + NWARPS_TOT * NUM_BINS;  // [5][256]
    float* red = smem + 2 * NWARPS_TOT * NUM_BINS;
    #pragma unroll
    for (int j = 0; j < 8; j++) {
        sS[warp * NUM_BINS + lane + j * 32] = accS[j];
        sC[warp * NUM_BINS + lane + j * 32] = accC[j];
    }
    __syncthreads();

    for (int bin = tid; bin < NUM_BINS; bin += NTHREADS) {
        float s = 0.f, c = 0.f;
        #pragma unroll
        for (int w = 0; w < NWARPS_TOT; w++) {
            s += sS[w * NUM_BINS + bin];
            c += sC[w * NUM_BINS + bin];
        }
        float mean = s / fmaxf(c, 1.0f);   // empty segment -> 0
        float dv   = mean - target_mean[bin];
        red[bin]   = dv * dv;
    }
    __syncthreads();

    #pragma unroll
    for (int off = NUM_BINS / 2; off > 0; off >>= 1) {
        if (tid < off) red[tid] += red[tid + off];
        __syncthreads();
    }
    if (tid == 0) {
        out[0] = red[0] * (0.01f / (float)NUM_BINS);
        g_ticket = 0;                      // reset for next graph replay
    }
}

extern "C" void kernel_launch(void* const* d_in, const int* in_sizes, int n_in,
                              void* d_out, int out_size)
{
    const float* x   = (const float*)d_in[0];
    const int*   idx = (const int*)d_in[1];
    const float* tm  = (const float*)d_in[2];
    float*       out = (float*)d_out;
    const int E = in_sizes[0];

    cudaFuncSetAttribute(seg_hist_kernel,
                         cudaFuncAttributeMaxDynamicSharedMemorySize,
                         SMEM_BYTES);

    seg_hist_kernel<<<GRID, NTHREADS, SMEM_BYTES>>>(x, idx, tm, out, E);
}

// round 13
// speedup vs baseline: 1.0006x; 1.0006x over previous
#include <cuda_runtime.h>
#include <stdint.h>

#define NUM_BINS   256
#define GRID       152                 // GB300: 152 SMs, 1 resident block each
#define NC_WARPS   4                   // consumer warps (own histograms)
#define NWARPS_TOT 5                   // + 1 producer warp
#define CTHREADS   (NC_WARPS * 32)     // 128
#define NTHREADS   (NWARPS_TOT * 32)   // 160

#define HIST_F32_PER_WARP (NUM_BINS * 32)            // 8192 floats = 32 KB
#define HIST_FLOATS (NC_WARPS * HIST_F32_PER_WARP)   // 32768
#define HIST_BYTES  (HIST_FLOATS * 4)                // 131072

#define GPT         8                  // float4-groups per consumer thread per slot
#define SLOT_G      (CTHREADS * GPT)   // 1024 groups = 4096 elements
#define SLOT_HALF   (SLOT_G * 16)      // 16384 B (x half; idx half same)
#define SLOT_BYTES  (SLOT_G * 32)      // 32768 B
#define NSLOTS      3
#define RING_BYTES  (NSLOTS * SLOT_BYTES)            // 98304
#define MBAR_BYTES  128
#define SMEM_BYTES  (HIST_BYTES + RING_BYTES + MBAR_BYTES)  // 229504 <= 232448

#define BIAS 1024.0f
#define INV_BIAS (1.0f / 1024.0f)

// per-block partial results + completion ticket (no cudaMalloc allowed)
__device__ float g_psum[GRID * NUM_BINS];
__device__ float g_pcnt[GRID * NUM_BINS];
__device__ int   g_ticket = 0;

__device__ __forceinline__ uint32_t smem_u32(const void* p) {
    return (uint32_t)__cvta_generic_to_shared(p);
}
__device__ __forceinline__ void mbar_init(uint32_t mbar, uint32_t cnt) {
    asm volatile("mbarrier.init.shared.b64 [%0], %1;" :: "r"(mbar), "r"(cnt) : "memory");
}
__device__ __forceinline__ void mbar_arrive(uint32_t mbar) {
    asm volatile("mbarrier.arrive.shared.b64 _, [%0];" :: "r"(mbar) : "memory");
}
__device__ __forceinline__ void mbar_expect_tx(uint32_t mbar, uint32_t bytes) {
    asm volatile("mbarrier.arrive.expect_tx.shared.b64 _, [%0], %1;"
                 :: "r"(mbar), "r"(bytes) : "memory");
}
__device__ __forceinline__ void mbar_wait(uint32_t mbar, uint32_t phase) {
    asm volatile(
        "{\n\t"
        ".reg .pred P1;\n\t"
        "WAIT_LOOP_%=:\n\t"
        "mbarrier.try_wait.parity.acquire.cta.shared::cta.b64 P1, [%0], %1, 0x989680;\n\t"
        "@P1 bra.uni WAIT_DONE_%=;\n\t"
        "bra.uni WAIT_LOOP_%=;\n\t"
        "WAIT_DONE_%=:\n\t"
        "}"
        :: "r"(mbar), "r"(phase) : "memory");
}
__device__ __forceinline__ void bulk_g2s(uint32_t sdst, const void* gsrc,
                                         uint32_t bytes, uint32_t mbar) {
    asm volatile(
        "cp.async.bulk.shared::cta.global.mbarrier::complete_tx::bytes "
        "[%0], [%1], %2, [%3];"
        :: "r"(sdst), "l"(gsrc), "r"(bytes), "r"(mbar) : "memory");
}

// 4-way wave: exact dedup in registers, then 4 batched LDS + <=4 predicated STS.
__device__ __forceinline__ void rmw4d(float* hb, float4 xv, int4 iv) {
    int b0 = iv.x & 255, b1 = iv.y & 255, b2 = iv.z & 255, b3 = iv.w & 255;
    float v0 = xv.x + BIAS, v1 = xv.y + BIAS, v2 = xv.z + BIAS, v3 = xv.w + BIAS;

    bool l1 = (b1 != b0);
    if (!l1) v0 += v1;

    bool e20 = (b2 == b0);
    bool e21 = (b2 == b1) && l1;
    bool l2  = !(e20 || e21);
    if (e20) v0 += v2;
    if (e21) v1 += v2;

    bool e30 = (b3 == b0);
    bool e31 = (b3 == b1) && l1;
    bool e32 = (b3 == b2) && l2;
    bool l3  = !(e30 || e31 || e32);
    if (e30) v0 += v3;
    if (e31) v1 += v3;
    if (e32) v2 += v3;

    float* p0 = hb + (b0 << 5);
    float* p1 = hb + (b1 << 5);
    float* p2 = hb + (b2 << 5);
    float* p3 = hb + (b3 << 5);
    float e0 = *p0;
    float f1 = *p1;
    float f2 = *p2;
    float f3 = *p3;
    *p0 = e0 + v0;
    if (l1) *p1 = f1 + v1;
    if (l2) *p2 = f2 + v2;
    if (l3) *p3 = f3 + v3;
}

__global__ __launch_bounds__(NTHREADS, 1)
void seg_hist_kernel(const float* __restrict__ x,
                     const int*   __restrict__ idx,
                     const float* __restrict__ target_mean,
                     float* __restrict__ out,
                     int E)
{
    extern __shared__ float smem[];
    const int tid  = threadIdx.x;
    const int lane = tid & 31;
    const int warp = tid >> 5;
    const int bid  = blockIdx.x;

    char*    ring = (char*)smem + HIST_BYTES;
    uint32_t mb   = smem_u32((char*)smem + HIST_BYTES + RING_BYTES);
    // full[s] = mb + s*16 ; empty[s] = mb + s*16 + 8

    // zero the private histograms (vectorized)
    float4* sz = (float4*)smem;
    #pragma unroll 4
    for (int i = tid; i < HIST_FLOATS / 4; i += NTHREADS)
        sz[i] = make_float4(0.f, 0.f, 0.f, 0.f);

    if (tid == 0) {
        #pragma unroll
        for (int s = 0; s < NSLOTS; s++) {
            mbar_init(mb + s * 16,     1);         // full: producer expect_tx
            mbar_init(mb + s * 16 + 8, NC_WARPS);  // empty: 1 arrive per consumer warp
        }
    }
    __syncthreads();

    const float4* __restrict__ x4 = (const float4*)x;
    const int4*   __restrict__ i4 = (const int4*)idx;
    const int G = E >> 2;                        // float4 groups (2^23)
    const int total_slots = G / SLOT_G;          // 8192
    const int tail_start  = total_slots * SLOT_G;
    const int nslots = total_slots / GRID + (bid < (total_slots % GRID) ? 1 : 0);

    if (warp < NC_WARPS) {
        // ── consumer: wait full, STAGE slot into registers, release slot
        //    immediately (early empty-arrive), then drain registers into the
        //    private histogram while the producer refills the slot.
        float* hb = smem + warp * HIST_F32_PER_WARP + lane;
        int s = 0, ph = 0;
        for (int i = 0; i < nslots; ++i) {
            mbar_wait(mb + s * 16, ph);
            const char* sl = ring + s * SLOT_BYTES;
            float4 a[GPT]; int4 b[GPT];
            #pragma unroll
            for (int k = 0; k < GPT; k++) {
                a[k] = *(const float4*)(sl + (k * CTHREADS + tid) * 16);
                b[k] = *(const int4*)(sl + SLOT_HALF + (k * CTHREADS + tid) * 16);
            }
            __syncwarp();
            if (lane == 0) mbar_arrive(mb + s * 16 + 8);   // release BEFORE drain
            #pragma unroll
            for (int k = 0; k < GPT; k++)
                rmw4d(hb, a[k], b[k]);
            if (++s == NSLOTS) { s = 0; ph ^= 1; }
        }
        // tail groups beyond full slots (direct bounds-checked loads)
        for (int g = tail_start + bid * CTHREADS + tid; g < G; g += GRID * CTHREADS)
            rmw4d(hb, __ldcs(&x4[g]), __ldcs(&i4[g]));

        // sub-float4 remainder: block 0, consumer warp 0
        int rem = E & 3;
        if (rem && bid == 0 && warp == 0 && lane < rem) {
            int e = (E & ~3) + lane;
            float v = x[e] + BIAS;
            float* p = hb + ((idx[e] & 255) << 5);
            *p = *p + v;
        }
    } else if (lane == 0) {
        // ── producer: single thread; bulk-copy contiguous slots, expect_tx
        int s = 0, ph = 1;                 // phase 1: first empty-wait passes
        for (int i = 0; i < nslots; ++i) {
            mbar_wait(mb + s * 16 + 8, ph);
            int sid = bid + i * GRID;
            uint32_t sdst = smem_u32(ring + s * SLOT_BYTES);
            mbar_expect_tx(mb + s * 16, SLOT_BYTES);
            bulk_g2s(sdst,             &x4[(size_t)sid * SLOT_G], SLOT_HALF, mb + s * 16);
            bulk_g2s(sdst + SLOT_HALF, &i4[(size_t)sid * SLOT_G], SLOT_HALF, mb + s * 16);
            if (++s == NSLOTS) { s = 0; ph ^= 1; }
        }
    }
    __syncthreads();

    // block reduction: NC_WARPS*32 lane-columns -> 1 (sum, count) per bin
    for (int bin = tid; bin < NUM_BINS; bin += NTHREADS) {
        float s = 0.0f, c = 0.0f;
        #pragma unroll
        for (int w = 0; w < NC_WARPS; w++) {
            const float* bptr = smem + w * HIST_F32_PER_WARP + (bin << 5);
            #pragma unroll
            for (int k = 0; k < 32; k++) {
                int l = (bin + k) & 31;          // rotated, conflict-free
                float e = bptr[l];
                float cc = rintf(e * INV_BIAS);  // recover count
                s += e - cc * BIAS;              // recover sum(x)
                c += cc;
            }
        }
        g_psum[bid * NUM_BINS + bin] = s;
        g_pcnt[bid * NUM_BINS + bin] = c;
    }
    __syncthreads();
    __threadfence();

    // last block finishes the reduction
    __shared__ int s_last;
    if (tid == 0)
        s_last = (atomicAdd(&g_ticket, 1) == GRID - 1) ? 1 : 0;
    __syncthreads();
    if (!s_last) return;

    // warp w sums blocks {w, w+5, ...} for all 256 bins (coalesced, L2-hot)
    float accS[8], accC[8];
    #pragma unroll
    for (int j = 0; j < 8; j++) { accS[j] = 0.f; accC[j] = 0.f; }
    for (int blk = warp; blk < GRID; blk += NWARPS_TOT) {
        #pragma unroll
        for (int j = 0; j < 8; j++) {
            int bin = lane + j * 32;
            accS[j] += g_psum[blk * NUM_BINS + bin];
            accC[j] += g_pcnt[blk * NUM_BINS + bin];
        }
    }
    float* sS  = smem;                          // [5][256]
    float* sC  = smem + NWARPS_TOT * NUM_BINS;  // [5][256]
    float* red = smem + 2 * NWARPS_TOT * NUM_BINS;
    #pragma unroll
    for (int j = 0; j < 8; j++) {
        sS[warp * NUM_BINS + lane + j * 32] = accS[j];
        sC[warp * NUM_BINS + lane + j * 32] = accC[j];
    }
    __syncthreads();

    for (int bin = tid; bin < NUM_BINS; bin += NTHREADS) {
        float s = 0.f, c = 0.f;
        #pragma unroll
        for (int w = 0; w < NWARPS_TOT; w++) {
            s += sS[w * NUM_BINS + bin];
            c += sC[w * NUM_BINS + bin];
        }
        float mean = s / fmaxf(c, 1.0f);   // empty segment -> 0
        float dv   = mean - target_mean[bin];
        red[bin]   = dv * dv;
    }
    __syncthreads();

    #pragma unroll
    for (int off = NUM_BINS / 2; off > 0; off >>= 1) {
        if (tid < off) red[tid] += red[tid + off];
        __syncthreads();
    }
    if (tid == 0) {
        out[0] = red[0] * (0.01f / (float)NUM_BINS);
        g_ticket = 0;                      // reset for next graph replay
    }
}

extern "C" void kernel_launch(void* const* d_in, const int* in_sizes, int n_in,
                              void* d_out, int out_size)
{
    const float* x   = (const float*)d_in[0];
    const int*   idx = (const int*)d_in[1];
    const float* tm  = (const float*)d_in[2];
    float*       out = (float*)d_out;
    const int E = in_sizes[0];

    cudaFuncSetAttribute(seg_hist_kernel,
                         cudaFuncAttributeMaxDynamicSharedMemorySize,
                         SMEM_BYTES);

    seg_hist_kernel<<<GRID, NTHREADS, SMEM_BYTES>>>(x, idx, tm, out, E);
}